// round 17
// baseline (speedup 1.0000x reference)
#include <cuda_runtime.h>
#include <cuda_bf16.h>
#include <cuda_fp16.h>
#include <cstdint>

#define BB 32
#define SS 128
#define TT 96
#define HH 1024
#define VV 32000
#define H3 3072
#define H2 2048
#define KSPLIT 8

// ---------------- scratch (static device globals; no allocation) ----------------
__device__ float g_values[BB * SS * HH];
__device__ float g_vw[BB * SS * HH];
__device__ float g_gi[BB * TT * H3];
__device__ float g_qwp[KSPLIT * BB * HH];
__device__ float g_h[BB * HH];
__device__ float g_gh[BB * H3];
__device__ float g_qw_all[BB * TT * HH];
__device__ float g_wsm[BB * TT * SS];
__device__ __nv_bfloat16 g_hhi[BB * HH];
__device__ __nv_bfloat16 g_hlo[BB * HH];
__device__ __nv_bfloat16 g_ahi[4096 * 2048];
__device__ __nv_bfloat16 g_alo[4096 * 2048];
__device__ __nv_bfloat16 g_a2hi[4096 * 1024];
__device__ __nv_bfloat16 g_a2lo[4096 * 1024];
__device__ __nv_bfloat16 g_whi[2048 * 2048];
__device__ __nv_bfloat16 g_wlo[2048 * 2048];
__device__ __nv_bfloat16 g_wihhi[H3 * HH];
__device__ __nv_bfloat16 g_wihlo[H3 * HH];
__device__ __nv_bfloat16 g_eihi[BB * TT * HH];
__device__ __nv_bfloat16 g_eilo[BB * TT * HH];
__device__ __nv_bfloat16 g_whhThi[H3 * HH];
__device__ __nv_bfloat16 g_whhTlo[H3 * HH];
__device__ __half g_c16hi[BB * TT * H2];
__device__ __half g_c16lo[BB * TT * H2];
__device__ __half g_w16[32000u * 2048u];
__device__ __half g_w16q[HH * HH];

// ---------------- fast transcendentals ------------------------------------------
__device__ __forceinline__ float ex2f(float x) {
    float y; asm("ex2.approx.f32 %0, %1;" : "=f"(y) : "f"(x)); return y;
}
__device__ __forceinline__ float rcpf(float x) {
    float y; asm("rcp.approx.f32 %0, %1;" : "=f"(y) : "f"(x)); return y;
}
__device__ __forceinline__ float sigmf(float x) {
    return rcpf(1.0f + ex2f(-1.4426950408889634f * x));
}
__device__ __forceinline__ float tanhx(float x) {
    float e = ex2f(2.8853900817779268f * x);
    return 1.0f - 2.0f * rcpf(e + 1.0f);
}

__device__ __forceinline__ uint32_t smem_to_u32(const void* p) {
    uint32_t a;
    asm("{ .reg .u64 t; cvta.to.shared.u64 t, %1; cvt.u32.u64 %0, t; }" : "=r"(a) : "l"(p));
    return a;
}

// ---------------- mma.sync primitives --------------------------------------------
__device__ __forceinline__ void ldsm_x4(uint32_t* r, uint32_t addr) {
    asm volatile("ldmatrix.sync.aligned.m8n8.x4.shared.b16 {%0,%1,%2,%3}, [%4];"
        : "=r"(r[0]), "=r"(r[1]), "=r"(r[2]), "=r"(r[3]) : "r"(addr));
}
__device__ __forceinline__ void mma16816(float* d, const uint32_t* a, uint32_t b0, uint32_t b1) {
    asm volatile("mma.sync.aligned.m16n8k16.row.col.f32.bf16.bf16.f32 "
        "{%0,%1,%2,%3}, {%4,%5,%6,%7}, {%8,%9}, {%0,%1,%2,%3};"
        : "+f"(d[0]), "+f"(d[1]), "+f"(d[2]), "+f"(d[3])
        : "r"(a[0]), "r"(a[1]), "r"(a[2]), "r"(a[3]), "r"(b0), "r"(b1));
}
__device__ __forceinline__ void mma16816h(float* d, const uint32_t* a, uint32_t b0, uint32_t b1) {
    asm volatile("mma.sync.aligned.m16n8k16.row.col.f32.f16.f16.f32 "
        "{%0,%1,%2,%3}, {%4,%5,%6,%7}, {%8,%9}, {%0,%1,%2,%3};"
        : "+f"(d[0]), "+f"(d[1]), "+f"(d[2]), "+f"(d[3])
        : "r"(a[0]), "r"(a[1]), "r"(a[2]), "r"(a[3]), "r"(b0), "r"(b1));
}
__device__ __forceinline__ void cp16(uint32_t dst, const void* src) {
    asm volatile("cp.async.cg.shared.global [%0], [%1], 16;" :: "r"(dst), "l"(src));
}

// ---------------- conversion kernels ---------------------------------------------
__global__ void wconv_kernel(const float* __restrict__ W, __nv_bfloat16* __restrict__ whi,
                             __nv_bfloat16* __restrict__ wlo, int K, int N) {
    __shared__ float t[32][33];
    int n0 = blockIdx.x * 32, k0 = blockIdx.y * 32;
    int tx = threadIdx.x, ty = threadIdx.y;
#pragma unroll
    for (int j = 0; j < 4; j++)
        t[ty + 8 * j][tx] = W[(long)(k0 + ty + 8 * j) * N + n0 + tx];
    __syncthreads();
#pragma unroll
    for (int j = 0; j < 4; j++) {
        int n = n0 + ty + 8 * j;
        float x = t[tx][ty + 8 * j];
        __nv_bfloat16 h = __float2bfloat16(x);
        float r = x - __bfloat162float(h);
        long o = (long)n * K + k0 + tx;
        whi[o] = h;
        wlo[o] = __float2bfloat16(r);
    }
}

__global__ void wconv16_kernel(const float* __restrict__ W, __half* __restrict__ w16,
                               int K, int N) {
    __shared__ float t[32][33];
    int n0 = blockIdx.x * 32, k0 = blockIdx.y * 32;
    int tx = threadIdx.x, ty = threadIdx.y;
#pragma unroll
    for (int j = 0; j < 4; j++)
        t[ty + 8 * j][tx] = W[(long)(k0 + ty + 8 * j) * N + n0 + tx];
    __syncthreads();
#pragma unroll
    for (int j = 0; j < 4; j++) {
        int n = n0 + ty + 8 * j;
        w16[(long)n * K + k0 + tx] = __float2half_rn(t[tx][ty + 8 * j]);
    }
}

__global__ void aconv_kernel(const float* __restrict__ A, __nv_bfloat16* __restrict__ ahi,
                             __nv_bfloat16* __restrict__ alo, int n) {
    int i = blockIdx.x * 256 + threadIdx.x;
    if (i >= n) return;
    float x = A[i];
    __nv_bfloat16 h = __float2bfloat16(x);
    ahi[i] = h;
    alo[i] = __float2bfloat16(x - __bfloat162float(h));
}

__global__ void aconv_gather_kernel(const float* __restrict__ emb, const int* __restrict__ idx,
                                    __nv_bfloat16* __restrict__ ahi, __nv_bfloat16* __restrict__ alo,
                                    int n) {
    int i = blockIdx.x * 256 + threadIdx.x;
    if (i >= n) return;
    int r = i >> 10, k = i & 1023;
    float x = emb[(long)idx[r] * HH + k];
    __nv_bfloat16 h = __float2bfloat16(x);
    ahi[i] = h;
    alo[i] = __float2bfloat16(x - __bfloat162float(h));
}

// ---------------- bf16 3-product HMMA GEMM ----------------------------------------
#define MM_PITCH 40
#define MM_MAT (128 * MM_PITCH * 2)
#define MM_STAGE (4 * MM_MAT)
#define MM_SMEM (2 * MM_STAGE)

__global__ __launch_bounds__(256, 2)
void mma_gemm_kernel(const __nv_bfloat16* __restrict__ Ahi, const __nv_bfloat16* __restrict__ Alo,
                     const __nv_bfloat16* __restrict__ Bhi, const __nv_bfloat16* __restrict__ Blo,
                     const float* __restrict__ bias, float* __restrict__ C, int K, int N,
                     __nv_bfloat16* __restrict__ Chi, __nv_bfloat16* __restrict__ Clo) {
    extern __shared__ __align__(16) char smem[];
    const uint32_t sb = smem_to_u32(smem);
    const int tid = threadIdx.x;
    const int wid = tid >> 5, lane = tid & 31;
    const int m0 = blockIdx.x * 128, n0 = blockIdx.y * 128;
    const int wm = (wid >> 1) * 32;
    const int wn = (wid & 1) * 64;
    const int NC = K >> 5;

    const __nv_bfloat16* gp0 = Ahi + (long)m0 * K;
    const __nv_bfloat16* gp1 = Alo + (long)m0 * K;
    const __nv_bfloat16* gp2 = Bhi + (long)n0 * K;
    const __nv_bfloat16* gp3 = Blo + (long)n0 * K;

    const __nv_bfloat16* gptr[8];
    uint32_t soff[8];
#pragma unroll
    for (int j = 0; j < 8; j++) {
        int i = tid + j * 256;
        int mat = i >> 9, r = (i >> 2) & 127, s = i & 3;
        const __nv_bfloat16* g = (mat == 0) ? gp0 : (mat == 1) ? gp1 : (mat == 2) ? gp2 : gp3;
        gptr[j] = g + (long)r * K + s * 8;
        soff[j] = (uint32_t)(mat * MM_MAT + r * (MM_PITCH * 2) + s * 16);
    }

    float acc[2][8][4];
#pragma unroll
    for (int a = 0; a < 2; a++)
#pragma unroll
        for (int b = 0; b < 8; b++)
#pragma unroll
            for (int c = 0; c < 4; c++) acc[a][b][c] = 0.0f;

    const int arow = lane & 15;
    const int acol = (lane >> 4) << 3;
    const int brow = ((lane >> 4) << 3) + (lane & 7);
    const int bcol = ((lane >> 3) & 1) << 3;

    auto issue = [&](int c, int buf) {
        const uint32_t b0 = sb + buf * MM_STAGE;
#pragma unroll
        for (int j = 0; j < 8; j++) cp16(b0 + soff[j], gptr[j] + c * 32);
        asm volatile("cp.async.commit_group;" ::: "memory");
    };

    issue(0, 0);

    for (int c = 0; c < NC; c++) {
        const int buf = c & 1;
        if (c + 1 < NC) {
            issue(c + 1, buf ^ 1);
            asm volatile("cp.async.wait_group 1;" ::: "memory");
        } else {
            asm volatile("cp.async.wait_group 0;" ::: "memory");
        }
        __syncthreads();

        const uint32_t base = sb + buf * MM_STAGE;
#pragma unroll
        for (int ks = 0; ks < 2; ks++) {
            const int kc = ks * 16;
            uint32_t ah[2][4], al[2][4], bb[4][4];
#pragma unroll
            for (int tm = 0; tm < 2; tm++) {
                uint32_t ad = base + (uint32_t)(((wm + tm * 16 + arow) * MM_PITCH + kc + acol) * 2);
                ldsm_x4(ah[tm], ad);
                ldsm_x4(al[tm], ad + MM_MAT);
            }
#pragma unroll
            for (int gn = 0; gn < 4; gn++) {
                uint32_t bd = base + 2 * MM_MAT +
                    (uint32_t)(((wn + gn * 16 + brow) * MM_PITCH + kc + bcol) * 2);
                ldsm_x4(bb[gn], bd);
            }
#pragma unroll
            for (int tm = 0; tm < 2; tm++)
#pragma unroll
                for (int j = 0; j < 8; j++) {
                    uint32_t b0 = bb[j >> 1][(j & 1) * 2];
                    uint32_t b1 = bb[j >> 1][(j & 1) * 2 + 1];
                    mma16816(acc[tm][j], ah[tm], b0, b1);
                    mma16816(acc[tm][j], al[tm], b0, b1);
                }
#pragma unroll
            for (int gn = 0; gn < 4; gn++) {
                uint32_t bd = base + 3 * MM_MAT +
                    (uint32_t)(((wn + gn * 16 + brow) * MM_PITCH + kc + bcol) * 2);
                ldsm_x4(bb[gn], bd);
            }
#pragma unroll
            for (int tm = 0; tm < 2; tm++)
#pragma unroll
                for (int j = 0; j < 8; j++)
                    mma16816(acc[tm][j], ah[tm],
                             bb[j >> 1][(j & 1) * 2], bb[j >> 1][(j & 1) * 2 + 1]);
        }
        __syncthreads();
    }

#pragma unroll
    for (int tm = 0; tm < 2; tm++) {
        const int r0 = m0 + wm + tm * 16 + (lane >> 2);
#pragma unroll
        for (int j = 0; j < 8; j++) {
            const int col = n0 + wn + j * 8 + (lane & 3) * 2;
            float b0 = bias[col], b1 = bias[col + 1];
            float v0 = acc[tm][j][0] + b0, v1 = acc[tm][j][1] + b1;
            float v2 = acc[tm][j][2] + b0, v3 = acc[tm][j][3] + b1;
            long o0 = (long)r0 * N + col;
            long o1 = o0 + 8 * (long)N;
            C[o0] = v0; C[o0 + 1] = v1;
            C[o1] = v2; C[o1 + 1] = v3;
            if (Chi) {
                __nv_bfloat16 t0 = __float2bfloat16(v0), t1 = __float2bfloat16(v1);
                __nv_bfloat16 t2 = __float2bfloat16(v2), t3 = __float2bfloat16(v3);
                Chi[o0] = t0; Chi[o0 + 1] = t1; Chi[o1] = t2; Chi[o1 + 1] = t3;
                Clo[o0] = __float2bfloat16(v0 - __bfloat162float(t0));
                Clo[o0 + 1] = __float2bfloat16(v1 - __bfloat162float(t1));
                Clo[o1] = __float2bfloat16(v2 - __bfloat162float(t2));
                Clo[o1 + 1] = __float2bfloat16(v3 - __bfloat162float(t3));
            }
        }
    }
}

// ---------------- fp16 HMMA GEMM (TWO: A hi+lo; ADDC: C += result) ---------------
#define F6_MAT (128 * MM_PITCH * 2)

template <bool TWO, bool ADDC>
__global__ __launch_bounds__(256, 2)
void mma_f16_kernel(const __half* __restrict__ Ahi, const __half* __restrict__ Alo,
                    const __half* __restrict__ Bf, const float* __restrict__ bias,
                    float* __restrict__ C, int K, int N, int lda, int ldb) {
    constexpr int MATS = TWO ? 3 : 2;
    constexpr int STAGE = MATS * F6_MAT;
    constexpr int NCP = MATS * 2;
    extern __shared__ __align__(16) char smem[];
    const uint32_t sb = smem_to_u32(smem);
    const int tid = threadIdx.x;
    const int wid = tid >> 5, lane = tid & 31;
    const int m0 = blockIdx.x * 128, n0 = blockIdx.y * 128;
    const int wm = (wid >> 1) * 32;
    const int wn = (wid & 1) * 64;
    const int NC = K >> 5;
    const int bmat = (MATS - 1) * F6_MAT;

    const __half* gp0 = Ahi + (long)m0 * lda;
    const __half* gp1 = TWO ? (Alo + (long)m0 * lda) : nullptr;
    const __half* gp2 = Bf + (long)n0 * ldb;

    const __half* gptr[NCP];
    uint32_t soff[NCP];
#pragma unroll
    for (int j = 0; j < NCP; j++) {
        int i = tid + j * 256;
        int mat = i >> 9, r = (i >> 2) & 127, s = i & 3;
        const __half* g;
        if (mat == 0) g = gp0 + (long)r * lda;
        else if (TWO && mat == 1) g = gp1 + (long)r * lda;
        else g = gp2 + (long)r * ldb;
        gptr[j] = g + s * 8;
        soff[j] = (uint32_t)(mat * F6_MAT + r * (MM_PITCH * 2) + s * 16);
    }

    float acc[2][8][4];
#pragma unroll
    for (int a = 0; a < 2; a++)
#pragma unroll
        for (int b = 0; b < 8; b++)
#pragma unroll
            for (int c = 0; c < 4; c++) acc[a][b][c] = 0.0f;

    const int arow = lane & 15;
    const int acol = (lane >> 4) << 3;
    const int brow = ((lane >> 4) << 3) + (lane & 7);
    const int bcol = ((lane >> 3) & 1) << 3;

    auto issue = [&](int c, int buf) {
        const uint32_t b0 = sb + buf * STAGE;
#pragma unroll
        for (int j = 0; j < NCP; j++) cp16(b0 + soff[j], gptr[j] + c * 32);
        asm volatile("cp.async.commit_group;" ::: "memory");
    };

    issue(0, 0);

    for (int c = 0; c < NC; c++) {
        const int buf = c & 1;
        if (c + 1 < NC) {
            issue(c + 1, buf ^ 1);
            asm volatile("cp.async.wait_group 1;" ::: "memory");
        } else {
            asm volatile("cp.async.wait_group 0;" ::: "memory");
        }
        __syncthreads();

        const uint32_t base = sb + buf * STAGE;
#pragma unroll
        for (int ks = 0; ks < 2; ks++) {
            const int kc = ks * 16;
            uint32_t ah[2][4], al[2][4], bb[4][4];
#pragma unroll
            for (int tm = 0; tm < 2; tm++) {
                uint32_t ad = base + (uint32_t)(((wm + tm * 16 + arow) * MM_PITCH + kc + acol) * 2);
                ldsm_x4(ah[tm], ad);
                if (TWO) ldsm_x4(al[tm], ad + F6_MAT);
            }
#pragma unroll
            for (int gn = 0; gn < 4; gn++) {
                uint32_t bd = base + bmat +
                    (uint32_t)(((wn + gn * 16 + brow) * MM_PITCH + kc + bcol) * 2);
                ldsm_x4(bb[gn], bd);
            }
#pragma unroll
            for (int tm = 0; tm < 2; tm++)
#pragma unroll
                for (int j = 0; j < 8; j++) {
                    uint32_t b0 = bb[j >> 1][(j & 1) * 2];
                    uint32_t b1 = bb[j >> 1][(j & 1) * 2 + 1];
                    mma16816h(acc[tm][j], ah[tm], b0, b1);
                    if (TWO) mma16816h(acc[tm][j], al[tm], b0, b1);
                }
        }
        __syncthreads();
    }

#pragma unroll
    for (int tm = 0; tm < 2; tm++) {
        const int r0 = m0 + wm + tm * 16 + (lane >> 2);
#pragma unroll
        for (int j = 0; j < 8; j++) {
            const int col = n0 + wn + j * 8 + (lane & 3) * 2;
            long o0 = (long)r0 * N + col;
            long o1 = o0 + 8 * (long)N;
            if (ADDC) {
                C[o0] += acc[tm][j][0];
                C[o0 + 1] += acc[tm][j][1];
                C[o1] += acc[tm][j][2];
                C[o1 + 1] += acc[tm][j][3];
            } else {
                float b0 = bias[col], b1 = bias[col + 1];
                C[o0] = acc[tm][j][0] + b0;
                C[o0 + 1] = acc[tm][j][1] + b1;
                C[o1] = acc[tm][j][2] + b0;
                C[o1 + 1] = acc[tm][j][3] + b1;
            }
        }
    }
}

// ---------------- recurrence HMMA GEMM: gh[32,3072] = h @ Whh^T -------------------
#define RN_PITCH 72
#define RN_AMAT (32 * RN_PITCH * 2)
#define RN_BMAT (64 * RN_PITCH * 2)
#define RN_STAGE (2 * RN_AMAT + 2 * RN_BMAT)
#define RN_SMEM (2 * RN_STAGE)

__global__ __launch_bounds__(256, 2)
void rnn_gemm_kernel(const __nv_bfloat16* __restrict__ hhi, const __nv_bfloat16* __restrict__ hlo,
                     const __nv_bfloat16* __restrict__ bhi, const __nv_bfloat16* __restrict__ blo,
                     float* __restrict__ gh) {
    extern __shared__ __align__(16) char smem[];
    const uint32_t sb = smem_to_u32(smem);
    const int tid = threadIdx.x;
    const int wid = tid >> 5, lane = tid & 31;
    const int n0 = blockIdx.x * 64;
    const int wm2 = wid >> 2;
    const int wn2 = wid & 3;

    const __nv_bfloat16* gptr[6];
    uint32_t soff[6];
#pragma unroll
    for (int j = 0; j < 6; j++) {
        int i = tid + j * 256;
        if (i < 512) {
            int ii = i & 255;
            int r = ii >> 3, s = ii & 7;
            const __nv_bfloat16* g = (i < 256) ? hhi : hlo;
            gptr[j] = g + r * HH + s * 8;
            soff[j] = (uint32_t)((i < 256 ? 0 : RN_AMAT) + r * (RN_PITCH * 2) + s * 16);
        } else {
            int ii = (i - 512) & 511;
            int r = ii >> 3, s = ii & 7;
            const __nv_bfloat16* g = (i < 1024) ? bhi : blo;
            gptr[j] = g + (long)(n0 + r) * HH + s * 8;
            soff[j] = (uint32_t)(2 * RN_AMAT + (i < 1024 ? 0 : RN_BMAT) + r * (RN_PITCH * 2) + s * 16);
        }
    }

    float acc[2][4];
#pragma unroll
    for (int j = 0; j < 2; j++)
#pragma unroll
        for (int c = 0; c < 4; c++) acc[j][c] = 0.0f;

    const int arow = lane & 15;
    const int acol = (lane >> 4) << 3;
    const int brow = ((lane >> 4) << 3) + (lane & 7);
    const int bcol = ((lane >> 3) & 1) << 3;

    auto issue = [&](int c, int buf) {
        const uint32_t b0 = sb + buf * RN_STAGE;
#pragma unroll
        for (int j = 0; j < 6; j++) cp16(b0 + soff[j], gptr[j] + c * 64);
        asm volatile("cp.async.commit_group;" ::: "memory");
    };

    issue(0, 0);
    const int NC = HH / 64;
    for (int c = 0; c < NC; c++) {
        const int buf = c & 1;
        if (c + 1 < NC) {
            issue(c + 1, buf ^ 1);
            asm volatile("cp.async.wait_group 1;" ::: "memory");
        } else {
            asm volatile("cp.async.wait_group 0;" ::: "memory");
        }
        __syncthreads();

        const uint32_t base = sb + buf * RN_STAGE;
#pragma unroll
        for (int ks = 0; ks < 4; ks++) {
            const int kc = ks * 16;
            uint32_t ah[4], al[4], bh[4], bl[4];
            uint32_t ad = base + (uint32_t)(((wm2 * 16 + arow) * RN_PITCH + kc + acol) * 2);
            ldsm_x4(ah, ad);
            ldsm_x4(al, ad + RN_AMAT);
            uint32_t bd = base + 2 * RN_AMAT +
                (uint32_t)(((wn2 * 16 + brow) * RN_PITCH + kc + bcol) * 2);
            ldsm_x4(bh, bd);
            ldsm_x4(bl, bd + RN_BMAT);
#pragma unroll
            for (int j = 0; j < 2; j++) {
                mma16816(acc[j], ah, bh[j * 2], bh[j * 2 + 1]);
                mma16816(acc[j], al, bh[j * 2], bh[j * 2 + 1]);
                mma16816(acc[j], ah, bl[j * 2], bl[j * 2 + 1]);
            }
        }
        __syncthreads();
    }

    const int row = wm2 * 16 + (lane >> 2);
#pragma unroll
    for (int j = 0; j < 2; j++) {
        const int col = n0 + wn2 * 16 + j * 8 + (lane & 3) * 2;
        gh[row * H3 + col] = acc[j][0];
        gh[row * H3 + col + 1] = acc[j][1];
        gh[(row + 8) * H3 + col] = acc[j][2];
        gh[(row + 8) * H3 + col + 1] = acc[j][3];
    }
}

// ---------------- small-M fp32 split-K GEMM (h0 only) ----------------------------
__global__ void gemm_m32_kernel(const float* __restrict__ A, const float* __restrict__ Bm,
                                float* __restrict__ Cp, int N, int K, int ksplit) {
    extern __shared__ float sh[];
    const int kslice = K / ksplit;
    const int tid = threadIdx.x;
    const int k0 = blockIdx.y * kslice;

    for (int i = tid; i < 32 * kslice; i += 256) {
        int b = i / kslice;
        int k = i - b * kslice;
        sh[k * 33 + b] = A[b * K + k0 + k];
    }
    __syncthreads();

    const int w = tid >> 5, lane = tid & 31;
    const int n0 = blockIdx.x * 32 + w * 4;
    const float* Bp = Bm + (long)k0 * N + n0;
    float a0 = 0.f, a1 = 0.f, a2 = 0.f, a3 = 0.f;
#pragma unroll 8
    for (int k = 0; k < kslice; k++) {
        float4 wv = *(const float4*)(Bp + (long)k * N);
        float a = sh[k * 33 + lane];
        a0 += a * wv.x; a1 += a * wv.y; a2 += a * wv.z; a3 += a * wv.w;
    }
    float4* o = (float4*)(Cp + ((long)blockIdx.y * 32 + lane) * N + n0);
    *o = make_float4(a0, a1, a2, a3);
}

__global__ void reduce8_bias_kernel(const float* __restrict__ part, const float* __restrict__ bias,
                                    float* __restrict__ out, int n, int biasN) {
    int i = blockIdx.x * 256 + threadIdx.x;
    if (i >= n) return;
    float s = bias[i % biasN];
#pragma unroll
    for (int p = 0; p < KSPLIT; p++) s += part[(long)p * n + i];
    out[i] = s;
}

__global__ void hconv_kernel(const float* __restrict__ h, __nv_bfloat16* __restrict__ hhi,
                             __nv_bfloat16* __restrict__ hlo) {
    int i = blockIdx.x * 256 + threadIdx.x;
    if (i >= BB * HH) return;
    float x = h[i];
    __nv_bfloat16 t = __float2bfloat16(x);
    hhi[i] = t;
    hlo[i] = __float2bfloat16(x - __bfloat162float(t));
}

// ---------------- fused GRU gates ------------------------------------------------
__global__ void gates_kernel(const float* __restrict__ gi, const float* __restrict__ gh,
                             const float* __restrict__ bhh, float* __restrict__ h,
                             __nv_bfloat16* __restrict__ hhi, __nv_bfloat16* __restrict__ hlo,
                             __half* __restrict__ c16hi, __half* __restrict__ c16lo, int t) {
    int i = blockIdx.x * 256 + threadIdx.x;
    int b = i >> 10;
    int n = i & 1023;
    const float* g = gh + (long)b * H3;
    float hr = bhh[n] + g[n];
    float hz = bhh[HH + n] + g[HH + n];
    float hn = bhh[2 * HH + n] + g[2 * HH + n];
    const float* gir = gi + ((long)b * TT + t) * H3;
    float r = sigmf(gir[n] + hr);
    float z = sigmf(gir[HH + n] + hz);
    float nn = tanhx(gir[2 * HH + n] + r * hn);
    float hv = (1.0f - z) * nn + z * h[i];
    h[i] = hv;
    __nv_bfloat16 th = __float2bfloat16(hv);
    hhi[i] = th;
    hlo[i] = __float2bfloat16(hv - __bfloat162float(th));
    long co = ((long)b * TT + t) * H2 + n;
    __half f = __float2half_rn(hv);
    c16hi[co] = f;
    c16lo[co] = __float2half_rn(hv - __half2float(f));
}

// ---------------- batched scores + softmax ---------------------------------------
__global__ __launch_bounds__(256)
void scores_batch_kernel(const float* __restrict__ qw_all, const float* __restrict__ wc_g,
                         const float* __restrict__ bc, const int* __restrict__ mask,
                         const float* __restrict__ vw, float* __restrict__ wsm) {
    __shared__ float q[HH];
    __shared__ float wcs[HH];
    __shared__ float sc[SS];
    __shared__ float red[SS];
    const int blk = blockIdx.x;
    const int b = blk / TT;
    const int tid = threadIdx.x;
    for (int i = tid; i < HH; i += 256) {
        q[i] = qw_all[(long)blk * HH + i];
        wcs[i] = wc_g[i];
    }
    __syncthreads();
    const int w = tid >> 5, lane = tid & 31;
#pragma unroll
    for (int si = 0; si < 16; si++) {
        const int s = w * 16 + si;
        const float* v = vw + (long)(b * SS + s) * HH;
        float a = 0.0f;
        for (int hh = lane; hh < HH; hh += 32)
            a += wcs[hh] * tanhx(q[hh] + v[hh]);
#pragma unroll
        for (int off = 16; off > 0; off >>= 1) a += __shfl_xor_sync(0xffffffffu, a, off);
        if (lane == 0)
            sc[s] = a + bc[0] + (mask[b * SS + s] == 0 ? -1e30f : 0.0f);
    }
    __syncthreads();
    if (tid < 128) red[tid] = sc[tid];
    __syncthreads();
#pragma unroll
    for (int off = 64; off > 0; off >>= 1) {
        if (tid < off) red[tid] = fmaxf(red[tid], red[tid + off]);
        __syncthreads();
    }
    float mx = red[0];
    __syncthreads();
    float e = 0.0f;
    if (tid < 128) { e = ex2f((sc[tid] - mx) * 1.4426950408889634f); red[tid] = e; }
    __syncthreads();
#pragma unroll
    for (int off = 64; off > 0; off >>= 1) {
        if (tid < off) red[tid] += red[tid + off];
        __syncthreads();
    }
    if (tid < 128) wsm[(long)blk * SS + tid] = e * rcpf(red[0]);
}

// ---------------- batched context ------------------------------------------------
#define CTX_SMEM ((SS * 128 + SS) * 4)
__global__ __launch_bounds__(128)
void ctx_batch_kernel(const float* __restrict__ wsm, const float* __restrict__ values,
                      __half* __restrict__ c16hi) {
    extern __shared__ float csm[];
    float* val = csm;
    float* wv = csm + SS * 128;
    const int b = blockIdx.x;
    const int h0 = blockIdx.y * 128;
    const int tid = threadIdx.x;
    for (int s = 0; s < SS; s++)
        val[s * 128 + tid] = values[(long)(b * SS + s) * HH + h0 + tid];
    __syncthreads();
    for (int t = 0; t < TT; t++) {
        wv[tid] = wsm[((long)b * TT + t) * SS + tid];
        __syncthreads();
        float acc = 0.0f;
#pragma unroll 16
        for (int s = 0; s < SS; s++) acc += wv[s] * val[s * 128 + tid];
        long co = ((long)b * TT + t) * H2 + HH + h0 + tid;
        c16hi[co] = __float2half_rn(acc);
        __syncthreads();
    }
}

__global__ void copyh_kernel(const float* __restrict__ h, float* __restrict__ out) {
    int i = blockIdx.x * 256 + threadIdx.x;
    if (i < BB * HH) out[i] = h[i];
}

// ---------------- launch ----------------------------------------------------------
extern "C" void kernel_launch(void* const* d_in, const int* in_sizes, int n_in,
                              void* d_out, int out_size) {
    const float* enc_out = (const float*)d_in[0];
    const float* enc_hid = (const float*)d_in[1];
    const int*   mask    = (const int*)d_in[2];
    const int*   tgt     = (const int*)d_in[3];
    const float* emb     = (const float*)d_in[4];
    const float* Wq   = (const float*)d_in[5];
    const float* bq   = (const float*)d_in[6];
    const float* Wv   = (const float*)d_in[7];
    const float* bv   = (const float*)d_in[8];
    const float* wc   = (const float*)d_in[9];
    const float* bc   = (const float*)d_in[10];
    const float* Wih  = (const float*)d_in[11];
    const float* bih  = (const float*)d_in[12];
    const float* Whh  = (const float*)d_in[13];
    const float* bhh  = (const float*)d_in[14];
    const float* Wproj = (const float*)d_in[15];
    const float* bproj = (const float*)d_in[16];
    const float* Wout  = (const float*)d_in[17];
    const float* bout  = (const float*)d_in[18];
    float* out = (float*)d_out;

    float *values, *vw, *gi, *qwp, *h, *gh, *qw_all, *wsm;
    __nv_bfloat16 *hhi, *hlo, *ahi, *alo, *a2hi, *a2lo, *whi, *wlo;
    __nv_bfloat16 *wihhi, *wihlo, *eihi, *eilo, *whhThi, *whhTlo;
    __half *c16hi, *c16lo, *w16, *w16q;
    cudaGetSymbolAddress((void**)&values, g_values);
    cudaGetSymbolAddress((void**)&vw, g_vw);
    cudaGetSymbolAddress((void**)&gi, g_gi);
    cudaGetSymbolAddress((void**)&qwp, g_qwp);
    cudaGetSymbolAddress((void**)&h, g_h);
    cudaGetSymbolAddress((void**)&gh, g_gh);
    cudaGetSymbolAddress((void**)&qw_all, g_qw_all);
    cudaGetSymbolAddress((void**)&wsm, g_wsm);
    cudaGetSymbolAddress((void**)&hhi, g_hhi);
    cudaGetSymbolAddress((void**)&hlo, g_hlo);
    cudaGetSymbolAddress((void**)&ahi, g_ahi);
    cudaGetSymbolAddress((void**)&alo, g_alo);
    cudaGetSymbolAddress((void**)&a2hi, g_a2hi);
    cudaGetSymbolAddress((void**)&a2lo, g_a2lo);
    cudaGetSymbolAddress((void**)&whi, g_whi);
    cudaGetSymbolAddress((void**)&wlo, g_wlo);
    cudaGetSymbolAddress((void**)&wihhi, g_wihhi);
    cudaGetSymbolAddress((void**)&wihlo, g_wihlo);
    cudaGetSymbolAddress((void**)&eihi, g_eihi);
    cudaGetSymbolAddress((void**)&eilo, g_eilo);
    cudaGetSymbolAddress((void**)&whhThi, g_whhThi);
    cudaGetSymbolAddress((void**)&whhTlo, g_whhTlo);
    cudaGetSymbolAddress((void**)&c16hi, g_c16hi);
    cudaGetSymbolAddress((void**)&c16lo, g_c16lo);
    cudaGetSymbolAddress((void**)&w16, g_w16);
    cudaGetSymbolAddress((void**)&w16q, g_w16q);

    // attributes only where smem > 48KB (typed overload, as in R13/R14 which compiled)
    cudaFuncSetAttribute(mma_gemm_kernel, cudaFuncAttributeMaxDynamicSharedMemorySize, MM_SMEM);
    cudaFuncSetAttribute(mma_f16_kernel<true, false>, cudaFuncAttributeMaxDynamicSharedMemorySize, 2 * 3 * F6_MAT);
    cudaFuncSetAttribute(rnn_gemm_kernel, cudaFuncAttributeMaxDynamicSharedMemorySize, RN_SMEM);
    cudaFuncSetAttribute(ctx_batch_kernel, cudaFuncAttributeMaxDynamicSharedMemorySize, CTX_SMEM);

    // one-time stream/event resources (host-side only; per-call work identical)
    static cudaStream_t s2 = nullptr;
    static cudaEvent_t evF = nullptr, evG = nullptr, evJ = nullptr, evL = nullptr, evH = nullptr;
    static bool tried = false;
    if (!tried) {
        tried = true;
        bool ok = cudaStreamCreateWithFlags(&s2, cudaStreamNonBlocking) == cudaSuccess;
        ok = ok && cudaEventCreateWithFlags(&evF, cudaEventDisableTiming) == cudaSuccess;
        ok = ok && cudaEventCreateWithFlags(&evG, cudaEventDisableTiming) == cudaSuccess;
        ok = ok && cudaEventCreateWithFlags(&evJ, cudaEventDisableTiming) == cudaSuccess;
        ok = ok && cudaEventCreateWithFlags(&evL, cudaEventDisableTiming) == cudaSuccess;
        ok = ok && cudaEventCreateWithFlags(&evH, cudaEventDisableTiming) == cudaSuccess;
        if (!ok) s2 = nullptr;
    }
    const bool fork = (s2 != nullptr);
    cudaStream_t sA = fork ? s2 : (cudaStream_t)0;

    // ---- fork ----
    if (fork) {
        cudaEventRecord(evF, 0);
        cudaStreamWaitEvent(s2, evF, 0);
    }

    // ---- side stream: gi path FIRST (loop-critical), then attention/logits prep --
    wconv_kernel<<<dim3(H3 / 32, HH / 32), dim3(32, 8), 0, sA>>>(Wih, wihhi, wihlo, HH, H3);
    aconv_gather_kernel<<<(BB * TT * HH) / 256, 256, 0, sA>>>(emb, tgt, eihi, eilo, BB * TT * HH);
    mma_gemm_kernel<<<dim3((BB * TT) / 128, H3 / 128), 256, MM_SMEM, sA>>>(
        eihi, eilo, wihhi, wihlo, bih, gi, HH, H3, nullptr, nullptr);
    if (fork) cudaEventRecord(evG, s2);
    wconv_kernel<<<dim3(HH / 32, H2 / 32), dim3(32, 8), 0, sA>>>(Wproj, whi, wlo, H2, HH);
    aconv_kernel<<<(4096 * 2048) / 256, 256, 0, sA>>>(enc_out, ahi, alo, 4096 * 2048);
    mma_gemm_kernel<<<dim3(4096 / 128, HH / 128), 256, MM_SMEM, sA>>>(
        ahi, alo, whi, wlo, bproj, values, H2, HH, a2hi, a2lo);
    wconv_kernel<<<dim3(HH / 32, HH / 32), dim3(32, 8), 0, sA>>>(Wv, whi, wlo, HH, HH);
    mma_gemm_kernel<<<dim3(4096 / 128, HH / 128), 256, MM_SMEM, sA>>>(
        a2hi, a2lo, whi, wlo, bv, vw, HH, HH, nullptr, nullptr);
    wconv16_kernel<<<dim3(VV / 32, H2 / 32), dim3(32, 8), 0, sA>>>(Wout, w16, H2, VV);
    wconv16_kernel<<<dim3(HH / 32, HH / 32), dim3(32, 8), 0, sA>>>(Wq, w16q, HH, HH);
    if (fork) cudaEventRecord(evJ, s2);

    // ---- main stream: Whh conv + h0 chain ----
    wconv_kernel<<<dim3(H3 / 32, HH / 32), dim3(32, 8)>>>(Whh, whhThi, whhTlo, HH, H3);
    gemm_m32_kernel<<<dim3(HH / 32, KSPLIT), 256, (H2 / KSPLIT) * 33 * 4>>>(enc_hid, Wproj, qwp, HH, H2, KSPLIT);
    reduce8_bias_kernel<<<(BB * HH + 255) / 256, 256>>>(qwp, bproj, h, BB * HH, HH);
    hconv_kernel<<<(BB * HH + 255) / 256, 256>>>(h, hhi, hlo);
    rnn_gemm_kernel<<<H3 / 64, 256, RN_SMEM>>>(hhi, hlo, whhThi, whhTlo, gh);

    // gi must be ready before step 0
    if (fork) cudaStreamWaitEvent((cudaStream_t)0, evG, 0);

    // ---- Phase B: serial recurrence ----
    for (int t = 0; t < TT; t++) {
        gates_kernel<<<(BB * HH) / 256, 256>>>(gi, gh, bhh, h, hhi, hlo, c16hi, c16lo, t);
        if (t + 1 < TT)
            rnn_gemm_kernel<<<H3 / 64, 256, RN_SMEM>>>(hhi, hlo, whhThi, whhTlo, gh);
    }
    if (fork) cudaEventRecord(evL, 0);

    // ---- side stream: h-half logits (K = 0..1023 of combined) overlaps attention -
    if (fork) cudaStreamWaitEvent(s2, evL, 0);
    mma_f16_kernel<false, false><<<dim3((BB * TT) / 128, VV / 128), 256, 2 * 2 * F6_MAT, sA>>>(
        c16hi, nullptr, w16, bout, out, HH, VV, H2, H2);
    if (fork) cudaEventRecord(evH, s2);

    // ---- main: batched attention ----
    if (fork) cudaStreamWaitEvent((cudaStream_t)0, evJ, 0);
    mma_f16_kernel<true, false><<<dim3((BB * TT) / 128, HH / 128), 256, 2 * 3 * F6_MAT>>>(
        c16hi, c16lo, w16q, bq, qw_all, HH, HH, H2, HH);
    scores_batch_kernel<<<BB * TT, 256>>>(qw_all, wc, bc, mask, vw, wsm);
    ctx_batch_kernel<<<dim3(BB, HH / 128), 128, CTX_SMEM>>>(wsm, values, c16hi);

    // ---- ctx-half logits: C += combined[:,1024:2048] @ Wout[1024:2048,:] ----
    if (fork) cudaStreamWaitEvent((cudaStream_t)0, evH, 0);
    mma_f16_kernel<false, true><<<dim3((BB * TT) / 128, VV / 128), 256, 2 * 2 * F6_MAT>>>(
        c16hi + HH, nullptr, w16 + HH, bout, out, HH, VV, H2, H2);

    long btv = (long)BB * TT * VV;
    if ((long)out_size >= btv + BB * HH)
        copyh_kernel<<<(BB * HH + 255) / 256, 256>>>(h, out + btv);
}